// round 15
// baseline (speedup 1.0000x reference)
#include <cuda_runtime.h>

// B=8, IC=512, H=W=64. Three launches:
//  k1   : channel-partial 1x1 conv — grid (64,32)=2048 blocks x 128 thr
//         (NCH=32: 2x threads -> ~55 warps/SM, higher aggregate MLP)
//  k1b2 : merge partials + stats (8 blocks x 1024); last block (ticket)
//         computes BN/PReLU/col-norm/mask -> g_scale4
//  kB   : out = x * scale (4096 x 256, best measured shape)

#define IC    512
#define HW    4096
#define HW4   1024
#define N4    8192        // 8 * HW4
#define NCH   32
#define CPC   16          // channels per chunk

__device__ float4   g_part4[NCH * N4];   // 4 MiB scratch
__device__ float4   g_m4[N4];            // m, [b][j4]
__device__ float    g_bsum[8];
__device__ float    g_bsum2[8];
__device__ float4   g_scale4[HW4];
__device__ unsigned g_cnt;               // zero-init; last user resets -> replay safe

// ---------------- k1: channel-partial 1x1 conv --------------------------
// grid (64, NCH) = 2048 blocks, block 128. Thread owns one (b,j4), 16 ch.
__global__ void k1_conv_partial(const float4* __restrict__ x4,
                                const float* __restrict__ w) {
    __shared__ float sw[CPC];
    const int tid = threadIdx.x;
    const int ch  = blockIdx.y;
    const int c0  = ch * CPC;
    if (tid < CPC) sw[tid] = w[c0 + tid];
    __syncthreads();

    const int n4 = blockIdx.x * 128 + tid;     // 0..8191
    const int b  = n4 >> 10;
    const int j4 = n4 & (HW4 - 1);
    const float4* xp = x4 + (size_t)(b * IC + c0) * HW4 + j4;

    float4 acc0 = make_float4(0.f, 0.f, 0.f, 0.f);
    float4 acc1 = make_float4(0.f, 0.f, 0.f, 0.f);
    #pragma unroll
    for (int c = 0; c < CPC; c += 2) {
        const float4 v0 = xp[(size_t)c * HW4];
        const float4 v1 = xp[(size_t)(c + 1) * HW4];
        const float  w0 = sw[c], w1 = sw[c + 1];
        acc0.x += v0.x * w0; acc0.y += v0.y * w0;
        acc0.z += v0.z * w0; acc0.w += v0.w * w0;
        acc1.x += v1.x * w1; acc1.y += v1.y * w1;
        acc1.z += v1.z * w1; acc1.w += v1.w * w1;
    }
    acc0.x += acc1.x; acc0.y += acc1.y; acc0.z += acc1.z; acc0.w += acc1.w;
    g_part4[ch * N4 + n4] = acc0;
}

__device__ __forceinline__ float4 bn_prelu4(float4 m, float mu, float rstd,
                                            float ga, float be, float p) {
    float4 X;
    X.x = (m.x - mu) * rstd * ga + be; X.x = (X.x > 0.f) ? X.x : p * X.x;
    X.y = (m.y - mu) * rstd * ga + be; X.y = (X.y > 0.f) ? X.y : p * X.y;
    X.z = (m.z - mu) * rstd * ga + be; X.z = (X.z > 0.f) ? X.z : p * X.z;
    X.w = (m.w - mu) * rstd * ga + be; X.w = (X.w > 0.f) ? X.w : p * X.w;
    return X;
}

// ---------------- k1b2: merge + stats, then ticketed mask phase ---------
// grid 8, block 1024. Thread merges one n4 (32 partials). Last block
// (cheap ticket) computes the mask with its 1024 threads (column tid).
__global__ void __launch_bounds__(1024, 1)
k1b2(const float* __restrict__ convb, const float* __restrict__ gamma,
     const float* __restrict__ beta,  const float* __restrict__ pw,
     const float* __restrict__ detal)
{
    __shared__ float s_red[32], s_red2[32];
    __shared__ float s_warp[32][8];
    __shared__ float s_mu, s_rstd, s_r[8];
    __shared__ int   s_last;

    const int tid = threadIdx.x;
    const int bid = blockIdx.x;
    const int warp = tid >> 5, lane = tid & 31;

    // ---- merge 32 partials -> m; per-block sums ----
    {
        const int n4 = (bid << 10) + tid;      // 0..8191
        const float c0 = convb[0];
        float4 v = make_float4(c0, c0, c0, c0);
        #pragma unroll
        for (int ch = 0; ch < NCH; ++ch) {
            const float4 p = g_part4[ch * N4 + n4];
            v.x += p.x; v.y += p.y; v.z += p.z; v.w += p.w;
        }
        g_m4[n4] = v;

        float s  = v.x + v.y + v.z + v.w;
        float s2 = v.x*v.x + v.y*v.y + v.z*v.z + v.w*v.w;
        #pragma unroll
        for (int o = 16; o > 0; o >>= 1) {
            s  += __shfl_down_sync(0xffffffffu, s,  o);
            s2 += __shfl_down_sync(0xffffffffu, s2, o);
        }
        if (lane == 0) { s_red[warp] = s; s_red2[warp] = s2; }
        __syncthreads();
        if (tid < 32) {
            s = s_red[tid]; s2 = s_red2[tid];
            #pragma unroll
            for (int o = 16; o > 0; o >>= 1) {
                s  += __shfl_down_sync(0xffffffffu, s,  o);
                s2 += __shfl_down_sync(0xffffffffu, s2, o);
            }
            if (tid == 0) { g_bsum[bid] = s; g_bsum2[bid] = s2; }
        }
    }

    // ---- ticket: last of 8 blocks runs the mask phase ----
    __threadfence();
    __syncthreads();
    if (tid == 0) s_last = (atomicAdd(&g_cnt, 1u) == 7u);
    __syncthreads();
    if (!s_last) return;
    if (tid == 0) g_cnt = 0u;                  // reset for next replay
    __threadfence();

    // ---- mask phase: 1024 threads, thread owns column tid ----
    if (tid < 8) {
        float s = 0.f, s2 = 0.f;
        #pragma unroll
        for (int i = 0; i < 8; ++i) { s += g_bsum[i]; s2 += g_bsum2[i]; }
        if (tid == 0) {
            const float mu  = s  * (1.0f / 32768.0f);
            const float var = s2 * (1.0f / 32768.0f) - mu * mu;
            s_mu = mu; s_rstd = rsqrtf(var + 1e-5f);
        }
    }
    __syncthreads();
    const float mu = s_mu, rstd = s_rstd;
    const float ga = gamma[0], be = beta[0], p = pw[0], dt = detal[0];

    float4 Xs[8];
    float4 n2 = make_float4(0.f, 0.f, 0.f, 0.f);
    #pragma unroll
    for (int b = 0; b < 8; ++b) {
        Xs[b] = bn_prelu4(g_m4[b * HW4 + tid], mu, rstd, ga, be, p);
        n2.x += Xs[b].x*Xs[b].x; n2.y += Xs[b].y*Xs[b].y;
        n2.z += Xs[b].z*Xs[b].z; n2.w += Xs[b].w*Xs[b].w;
    }
    float4 rs4;
    rs4.x = rsqrtf(n2.x); rs4.y = rsqrtf(n2.y);
    rs4.z = rsqrtf(n2.z); rs4.w = rsqrtf(n2.w);

    float rloc[8];
    #pragma unroll
    for (int b = 0; b < 8; ++b)
        rloc[b] = Xs[b].x*rs4.x + Xs[b].y*rs4.y + Xs[b].z*rs4.z + Xs[b].w*rs4.w;
    #pragma unroll
    for (int b = 0; b < 8; ++b)
        #pragma unroll
        for (int o = 16; o > 0; o >>= 1)
            rloc[b] += __shfl_down_sync(0xffffffffu, rloc[b], o);
    if (lane == 0) {
        #pragma unroll
        for (int b = 0; b < 8; ++b) s_warp[warp][b] = rloc[b];
    }
    __syncthreads();
    if (tid < 8) {
        float a = 0.f;
        #pragma unroll
        for (int wi = 0; wi < 32; ++wi) a += s_warp[wi][tid];
        s_r[tid] = a * (1.0f / 64.0f);
    }
    __syncthreads();

    float4 t4 = make_float4(0.f, 0.f, 0.f, 0.f);
    #pragma unroll
    for (int b = 0; b < 8; ++b) {
        const float rb = s_r[b];
        t4.x += Xs[b].x * rb; t4.y += Xs[b].y * rb;
        t4.z += Xs[b].z * rb; t4.w += Xs[b].w * rb;
    }
    const float Tx = t4.x * rs4.x, Ty = t4.y * rs4.y;
    const float Tz = t4.z * rs4.z, Tw = t4.w * rs4.w;
    const float gx = 50.0f/64.0f + 128.0f - 2.0f*Tx;
    const float gy = 50.0f/64.0f + 128.0f - 2.0f*Ty;
    const float gz = 50.0f/64.0f + 128.0f - 2.0f*Tz;
    const float gw = 50.0f/64.0f + 128.0f - 2.0f*Tw;
    float4 sc;
    sc.x = 1.0f + dt * (1.0f/64.0f - 0.01f * gx / (fabsf(gx) + 1e-8f));
    sc.y = 1.0f + dt * (1.0f/64.0f - 0.01f * gy / (fabsf(gy) + 1e-8f));
    sc.z = 1.0f + dt * (1.0f/64.0f - 0.01f * gz / (fabsf(gz) + 1e-8f));
    sc.w = 1.0f + dt * (1.0f/64.0f - 0.01f * gw / (fabsf(gw) + 1e-8f));
    g_scale4[tid] = sc;
}

// ---------------- kB: out = x * scale[j], 4 planes per thread -----------
// grid 4096, block 256 — best measured shape, plain ld/st.
__global__ void kB(const float4* __restrict__ x4, float4* __restrict__ out4) {
    const int t  = blockIdx.x * 256 + threadIdx.x;   // 0 .. 1048575
    const int j4 = t & (HW4 - 1);
    const int g  = t >> 10;                          // plane group 0..1023
    const float4 s = g_scale4[j4];
    const size_t base = (size_t)(g * 4) * HW4 + j4;

    float4 v0 = x4[base + 0 * HW4];
    float4 v1 = x4[base + 1 * HW4];
    float4 v2 = x4[base + 2 * HW4];
    float4 v3 = x4[base + 3 * HW4];
    v0.x *= s.x; v0.y *= s.y; v0.z *= s.z; v0.w *= s.w;
    v1.x *= s.x; v1.y *= s.y; v1.z *= s.z; v1.w *= s.w;
    v2.x *= s.x; v2.y *= s.y; v2.z *= s.z; v2.w *= s.w;
    v3.x *= s.x; v3.y *= s.y; v3.z *= s.z; v3.w *= s.w;
    out4[base + 0 * HW4] = v0;
    out4[base + 1 * HW4] = v1;
    out4[base + 2 * HW4] = v2;
    out4[base + 3 * HW4] = v3;
}

// ---------------- launch ------------------------------------------------
extern "C" void kernel_launch(void* const* d_in, const int* in_sizes, int n_in,
                              void* d_out, int out_size) {
    const float* x  = (const float*)d_in[0];
    const float* w  = (const float*)d_in[1];
    const float* cb = (const float*)d_in[2];
    const float* ga = (const float*)d_in[3];
    const float* be = (const float*)d_in[4];
    const float* pw = (const float*)d_in[5];
    const float* dt = (const float*)d_in[6];

    dim3 g1(64, NCH);
    k1_conv_partial<<<g1, 128>>>((const float4*)x, w);
    k1b2<<<8, 1024>>>(cb, ga, be, pw, dt);
    kB<<<4096, 256>>>((const float4*)x, (float4*)d_out);
}

// round 17
// speedup vs baseline: 1.0526x; 1.0526x over previous
#include <cuda_runtime.h>

// B=8, IC=512, H=W=64. Three launches chained with PDL:
//  k1   : channel-partial conv, grid(64,16) x 128 (R14 best: 14.0us)
//  k1b2 : PDL on k1. Triggers kB immediately, grid-syncs, then merge+
//         stats+ticketed mask -> g_scale4
//  kB   : PDL on k1b2. Issues x loads BEFORE grid-sync (overlaps k1b2),
//         then reads scale, multiplies, stores.

#define IC    512
#define HW    4096
#define HW4   1024
#define N4    8192        // 8 * HW4
#define NCH   16
#define CPC   32          // channels per chunk

__device__ float4   g_part4[NCH * N4];   // 2 MiB scratch
__device__ float4   g_m4[N4];            // m, [b][j4]
__device__ float    g_bsum[8];
__device__ float    g_bsum2[8];
__device__ float4   g_scale4[HW4];
__device__ unsigned g_cnt;               // zero-init; last user resets -> replay safe

// ---------------- k1: channel-partial 1x1 conv (R14 config) -------------
__global__ void k1_conv_partial(const float4* __restrict__ x4,
                                const float* __restrict__ w) {
    __shared__ float sw[CPC];
    const int tid = threadIdx.x;
    const int ch  = blockIdx.y;
    const int c0  = ch * CPC;
    if (tid < CPC) sw[tid] = w[c0 + tid];
    __syncthreads();

    const int n4 = blockIdx.x * 128 + tid;     // 0..8191
    const int b  = n4 >> 10;
    const int j4 = n4 & (HW4 - 1);
    const float4* xp = x4 + (size_t)(b * IC + c0) * HW4 + j4;

    float4 acc0 = make_float4(0.f, 0.f, 0.f, 0.f);
    float4 acc1 = make_float4(0.f, 0.f, 0.f, 0.f);
    #pragma unroll
    for (int c = 0; c < CPC; c += 2) {
        const float4 v0 = xp[(size_t)c * HW4];
        const float4 v1 = xp[(size_t)(c + 1) * HW4];
        const float  w0 = sw[c], w1 = sw[c + 1];
        acc0.x += v0.x * w0; acc0.y += v0.y * w0;
        acc0.z += v0.z * w0; acc0.w += v0.w * w0;
        acc1.x += v1.x * w1; acc1.y += v1.y * w1;
        acc1.z += v1.z * w1; acc1.w += v1.w * w1;
    }
    acc0.x += acc1.x; acc0.y += acc1.y; acc0.z += acc1.z; acc0.w += acc1.w;
    g_part4[ch * N4 + n4] = acc0;
}

__device__ __forceinline__ float4 bn_prelu4(float4 m, float mu, float rstd,
                                            float ga, float be, float p) {
    float4 X;
    X.x = (m.x - mu) * rstd * ga + be; X.x = (X.x > 0.f) ? X.x : p * X.x;
    X.y = (m.y - mu) * rstd * ga + be; X.y = (X.y > 0.f) ? X.y : p * X.y;
    X.z = (m.z - mu) * rstd * ga + be; X.z = (X.z > 0.f) ? X.z : p * X.z;
    X.w = (m.w - mu) * rstd * ga + be; X.w = (X.w > 0.f) ? X.w : p * X.w;
    return X;
}

// ---------------- k1b2: merge + stats + ticketed mask (PDL) -------------
__global__ void __launch_bounds__(1024, 1)
k1b2(const float* __restrict__ convb, const float* __restrict__ gamma,
     const float* __restrict__ beta,  const float* __restrict__ pw,
     const float* __restrict__ detal)
{
    __shared__ float s_red[32], s_red2[32];
    __shared__ float s_warp[32][8];
    __shared__ float s_mu, s_rstd, s_r[8];
    __shared__ int   s_last;

    const int tid = threadIdx.x;
    const int bid = blockIdx.x;
    const int warp = tid >> 5, lane = tid & 31;

    // Let kB start its x-load prologue right away (it grid-syncs on us
    // before touching g_scale4).
    cudaTriggerProgrammaticLaunchCompletion();
    // Wait for k1's partials to be visible.
    cudaGridDependencySynchronize();

    // ---- merge 16 partials -> m; per-block sums ----
    {
        const int n4 = (bid << 10) + tid;      // 0..8191
        const float c0 = convb[0];
        float4 v = make_float4(c0, c0, c0, c0);
        #pragma unroll
        for (int ch = 0; ch < NCH; ++ch) {
            const float4 p = g_part4[ch * N4 + n4];
            v.x += p.x; v.y += p.y; v.z += p.z; v.w += p.w;
        }
        g_m4[n4] = v;

        float s  = v.x + v.y + v.z + v.w;
        float s2 = v.x*v.x + v.y*v.y + v.z*v.z + v.w*v.w;
        #pragma unroll
        for (int o = 16; o > 0; o >>= 1) {
            s  += __shfl_down_sync(0xffffffffu, s,  o);
            s2 += __shfl_down_sync(0xffffffffu, s2, o);
        }
        if (lane == 0) { s_red[warp] = s; s_red2[warp] = s2; }
        __syncthreads();
        if (tid < 32) {
            s = s_red[tid]; s2 = s_red2[tid];
            #pragma unroll
            for (int o = 16; o > 0; o >>= 1) {
                s  += __shfl_down_sync(0xffffffffu, s,  o);
                s2 += __shfl_down_sync(0xffffffffu, s2, o);
            }
            if (tid == 0) { g_bsum[bid] = s; g_bsum2[bid] = s2; }
        }
    }

    // ---- ticket: last of 8 blocks runs the mask phase ----
    __threadfence();
    __syncthreads();
    if (tid == 0) s_last = (atomicAdd(&g_cnt, 1u) == 7u);
    __syncthreads();
    if (!s_last) return;
    if (tid == 0) g_cnt = 0u;                  // reset for next replay
    __threadfence();

    // ---- mask phase: 1024 threads, thread owns column tid ----
    if (tid < 8) {
        float s = 0.f, s2 = 0.f;
        #pragma unroll
        for (int i = 0; i < 8; ++i) { s += g_bsum[i]; s2 += g_bsum2[i]; }
        if (tid == 0) {
            const float mu  = s  * (1.0f / 32768.0f);
            const float var = s2 * (1.0f / 32768.0f) - mu * mu;
            s_mu = mu; s_rstd = rsqrtf(var + 1e-5f);
        }
    }
    __syncthreads();
    const float mu = s_mu, rstd = s_rstd;
    const float ga = gamma[0], be = beta[0], p = pw[0], dt = detal[0];

    float4 Xs[8];
    float4 n2 = make_float4(0.f, 0.f, 0.f, 0.f);
    #pragma unroll
    for (int b = 0; b < 8; ++b) {
        Xs[b] = bn_prelu4(g_m4[b * HW4 + tid], mu, rstd, ga, be, p);
        n2.x += Xs[b].x*Xs[b].x; n2.y += Xs[b].y*Xs[b].y;
        n2.z += Xs[b].z*Xs[b].z; n2.w += Xs[b].w*Xs[b].w;
    }
    float4 rs4;
    rs4.x = rsqrtf(n2.x); rs4.y = rsqrtf(n2.y);
    rs4.z = rsqrtf(n2.z); rs4.w = rsqrtf(n2.w);

    float rloc[8];
    #pragma unroll
    for (int b = 0; b < 8; ++b)
        rloc[b] = Xs[b].x*rs4.x + Xs[b].y*rs4.y + Xs[b].z*rs4.z + Xs[b].w*rs4.w;
    #pragma unroll
    for (int b = 0; b < 8; ++b)
        #pragma unroll
        for (int o = 16; o > 0; o >>= 1)
            rloc[b] += __shfl_down_sync(0xffffffffu, rloc[b], o);
    if (lane == 0) {
        #pragma unroll
        for (int b = 0; b < 8; ++b) s_warp[warp][b] = rloc[b];
    }
    __syncthreads();
    if (tid < 8) {
        float a = 0.f;
        #pragma unroll
        for (int wi = 0; wi < 32; ++wi) a += s_warp[wi][tid];
        s_r[tid] = a * (1.0f / 64.0f);
    }
    __syncthreads();

    float4 t4 = make_float4(0.f, 0.f, 0.f, 0.f);
    #pragma unroll
    for (int b = 0; b < 8; ++b) {
        const float rb = s_r[b];
        t4.x += Xs[b].x * rb; t4.y += Xs[b].y * rb;
        t4.z += Xs[b].z * rb; t4.w += Xs[b].w * rb;
    }
    const float Tx = t4.x * rs4.x, Ty = t4.y * rs4.y;
    const float Tz = t4.z * rs4.z, Tw = t4.w * rs4.w;
    const float gx = 50.0f/64.0f + 128.0f - 2.0f*Tx;
    const float gy = 50.0f/64.0f + 128.0f - 2.0f*Ty;
    const float gz = 50.0f/64.0f + 128.0f - 2.0f*Tz;
    const float gw = 50.0f/64.0f + 128.0f - 2.0f*Tw;
    float4 sc;
    sc.x = 1.0f + dt * (1.0f/64.0f - 0.01f * gx / (fabsf(gx) + 1e-8f));
    sc.y = 1.0f + dt * (1.0f/64.0f - 0.01f * gy / (fabsf(gy) + 1e-8f));
    sc.z = 1.0f + dt * (1.0f/64.0f - 0.01f * gz / (fabsf(gz) + 1e-8f));
    sc.w = 1.0f + dt * (1.0f/64.0f - 0.01f * gw / (fabsf(gw) + 1e-8f));
    g_scale4[tid] = sc;
}

// ---------------- kB: PDL apply — x loads BEFORE grid-sync --------------
// grid 4096, block 256, 4 planes/thread.
__global__ void kB(const float4* __restrict__ x4, float4* __restrict__ out4) {
    const int t  = blockIdx.x * 256 + threadIdx.x;   // 0 .. 1048575
    const int j4 = t & (HW4 - 1);
    const int g  = t >> 10;                          // plane group 0..1023
    const size_t base = (size_t)(g * 4) * HW4 + j4;

    // x is a kernel input — no dependency on k1b2. Issue loads first.
    float4 v0 = x4[base + 0 * HW4];
    float4 v1 = x4[base + 1 * HW4];
    float4 v2 = x4[base + 2 * HW4];
    float4 v3 = x4[base + 3 * HW4];

    // Wait for k1b2's g_scale4 writes.
    cudaGridDependencySynchronize();
    const float4 s = g_scale4[j4];

    v0.x *= s.x; v0.y *= s.y; v0.z *= s.z; v0.w *= s.w;
    v1.x *= s.x; v1.y *= s.y; v1.z *= s.z; v1.w *= s.w;
    v2.x *= s.x; v2.y *= s.y; v2.z *= s.z; v2.w *= s.w;
    v3.x *= s.x; v3.y *= s.y; v3.z *= s.z; v3.w *= s.w;
    out4[base + 0 * HW4] = v0;
    out4[base + 1 * HW4] = v1;
    out4[base + 2 * HW4] = v2;
    out4[base + 3 * HW4] = v3;
}

// ---------------- launch ------------------------------------------------
extern "C" void kernel_launch(void* const* d_in, const int* in_sizes, int n_in,
                              void* d_out, int out_size) {
    const float* x  = (const float*)d_in[0];
    const float* w  = (const float*)d_in[1];
    const float* cb = (const float*)d_in[2];
    const float* ga = (const float*)d_in[3];
    const float* be = (const float*)d_in[4];
    const float* pw = (const float*)d_in[5];
    const float* dt = (const float*)d_in[6];

    dim3 g1(64, NCH);
    k1_conv_partial<<<g1, 128>>>((const float4*)x, w);

    cudaLaunchAttribute attr[1];
    attr[0].id = cudaLaunchAttributeProgrammaticStreamSerialization;
    attr[0].val.programmaticStreamSerializationAllowed = 1;

    {   // k1b2 with PDL on k1 (hides its launch ramp under k1's tail)
        cudaLaunchConfig_t cfg = {};
        cfg.gridDim  = dim3(8, 1, 1);
        cfg.blockDim = dim3(1024, 1, 1);
        cfg.stream   = 0;
        cfg.attrs    = attr;
        cfg.numAttrs = 1;
        const float* a0 = cb; const float* a1 = ga; const float* a2 = be;
        const float* a3 = pw; const float* a4 = dt;
        cudaLaunchKernelEx(&cfg, k1b2, a0, a1, a2, a3, a4);
    }
    {   // kB with PDL on k1b2 (x loads overlap k1b2's execution)
        cudaLaunchConfig_t cfg = {};
        cfg.gridDim  = dim3(4096, 1, 1);
        cfg.blockDim = dim3(256, 1, 1);
        cfg.stream   = 0;
        cfg.attrs    = attr;
        cfg.numAttrs = 1;
        const float4* xx = (const float4*)x;
        float4* oo = (float4*)d_out;
        cudaLaunchKernelEx(&cfg, kB, xx, oo);
    }
}